// round 1
// baseline (speedup 1.0000x reference)
#include <cuda_runtime.h>
#include <cuda_bf16.h>

#define D_MODEL 1024
#define D_FF    4096
#define N_EXP   8
#define N_TOK   4096   // 4 * 1024

// ---------------- scratch (__device__ globals; no allocation allowed) ----------------
__device__ float g_gate[N_TOK];
__device__ int   g_expert[N_TOK];
__device__ int   g_pos[N_TOK];
__device__ int   g_count[N_EXP];
__device__ int   g_offset[N_EXP + 1];
__device__ int   g_perm[N_TOK];                       // gathered row -> token id
__device__ float g_h[(size_t)N_TOK * D_FF];           // 64 MB hidden activations

// ---------------- kernel 0: zero the per-expert counters ----------------
__global__ void zero_counts_kernel() {
    if (threadIdx.x < N_EXP) g_count[threadIdx.x] = 0;
}

// ---------------- kernel 1: router (one warp per token) ----------------
__global__ void router_kernel(const float* __restrict__ x,
                              const float* __restrict__ rW,
                              const float* __restrict__ rb) {
    int warp = (blockIdx.x * blockDim.x + threadIdx.x) >> 5;
    int lane = threadIdx.x & 31;
    if (warp >= N_TOK) return;
    const float* xr = x + (size_t)warp * D_MODEL;

    float acc[N_EXP];
#pragma unroll
    for (int e = 0; e < N_EXP; e++) acc[e] = 0.f;

    for (int d = lane; d < D_MODEL; d += 32) {
        float xv = xr[d];
        const float* w = rW + d * N_EXP;
#pragma unroll
        for (int e = 0; e < N_EXP; e++) acc[e] += xv * w[e];
    }
#pragma unroll
    for (int e = 0; e < N_EXP; e++) {
#pragma unroll
        for (int off = 16; off; off >>= 1)
            acc[e] += __shfl_xor_sync(0xffffffffu, acc[e], off);
    }
    if (lane == 0) {
        float mx = -1e30f; int arg = 0;
#pragma unroll
        for (int e = 0; e < N_EXP; e++) {
            float l = acc[e] + rb[e];
            acc[e] = l;
            if (l > mx) { mx = l; arg = e; }   // first-max tie-break like jnp.argmax
        }
        float s = 0.f;
#pragma unroll
        for (int e = 0; e < N_EXP; e++) s += expf(acc[e] - mx);
        float gate = 1.0f / s;  // softmax prob of the argmax entry
        int pos = atomicAdd(&g_count[arg], 1);
        g_gate[warp]   = gate;
        g_expert[warp] = arg;
        g_pos[warp]    = pos;
    }
}

// ---------------- kernel 2: exclusive scan over 8 counts ----------------
__global__ void offsets_kernel() {
    int s = 0;
    g_offset[0] = 0;
#pragma unroll
    for (int e = 0; e < N_EXP; e++) { s += g_count[e]; g_offset[e + 1] = s; }
}

// ---------------- kernel 3: build permutation (gathered row -> token) ----------------
__global__ void perm_kernel() {
    int t = blockIdx.x * blockDim.x + threadIdx.x;
    if (t >= N_TOK) return;
    g_perm[g_offset[g_expert[t]] + g_pos[t]] = t;
}

// ---------------- tiled fp32 GEMMs ----------------
#define BM 64
#define BN 64
#define BK 16

// h = relu( x_gathered[cnt, D_MODEL] @ W1[e] (D_MODEL x D_FF) + b1[e] )
__global__ __launch_bounds__(256) void ffn1_kernel(const float* __restrict__ x,
                                                   const float* __restrict__ W1,
                                                   const float* __restrict__ b1) {
    const int e   = blockIdx.z;
    const int cnt = g_count[e];
    const int m0  = blockIdx.y * BM;
    if (m0 >= cnt) return;
    const int off = g_offset[e];
    const int n0  = blockIdx.x * BN;
    const float* W = W1 + (size_t)e * D_MODEL * D_FF;

    __shared__ float As[BK][BM + 4];
    __shared__ float Bs[BK][BN];

    const int t  = threadIdx.x;
    const int tx = t & 15;       // 0..15 -> 4 output cols each
    const int ty = t >> 4;       // 0..15 -> 4 output rows each

    // A-load mapping: each thread loads a float4 at (am, ak..ak+3)
    const int am = t >> 2;            // 0..63
    const int ak = (t & 3) << 2;      // 0,4,8,12
    const int gm_a   = m0 + am;
    const bool a_ok  = gm_a < cnt;
    const float* xrow = a_ok ? (x + (size_t)g_perm[off + gm_a] * D_MODEL) : x;

    // B-load mapping: each thread loads a float4 at (bk, bn..bn+3)
    const int bk = t >> 4;            // 0..15
    const int bn = (t & 15) << 2;     // 0..60

    float acc[4][4] = {};

    for (int k0 = 0; k0 < D_MODEL; k0 += BK) {
        float4 av = a_ok ? *(const float4*)(xrow + k0 + ak)
                         : make_float4(0.f, 0.f, 0.f, 0.f);
        As[ak + 0][am] = av.x;
        As[ak + 1][am] = av.y;
        As[ak + 2][am] = av.z;
        As[ak + 3][am] = av.w;
        float4 bv = *(const float4*)(W + (size_t)(k0 + bk) * D_FF + n0 + bn);
        *(float4*)&Bs[bk][bn] = bv;
        __syncthreads();
#pragma unroll
        for (int k = 0; k < BK; k++) {
            float4 a = *(const float4*)&As[k][ty << 2];
            float4 b = *(const float4*)&Bs[k][tx << 2];
            float aa[4] = {a.x, a.y, a.z, a.w};
            float bb[4] = {b.x, b.y, b.z, b.w};
#pragma unroll
            for (int i = 0; i < 4; i++)
#pragma unroll
                for (int j = 0; j < 4; j++) acc[i][j] += aa[i] * bb[j];
        }
        __syncthreads();
    }

    const float4 bias = *(const float4*)(b1 + (size_t)e * D_FF + n0 + (tx << 2));
    const float bb[4] = {bias.x, bias.y, bias.z, bias.w};
#pragma unroll
    for (int i = 0; i < 4; i++) {
        int gm = m0 + (ty << 2) + i;
        if (gm < cnt) {
            float4 hv;
            hv.x = fmaxf(acc[i][0] + bb[0], 0.f);
            hv.y = fmaxf(acc[i][1] + bb[1], 0.f);
            hv.z = fmaxf(acc[i][2] + bb[2], 0.f);
            hv.w = fmaxf(acc[i][3] + bb[3], 0.f);
            *(float4*)&g_h[(size_t)(off + gm) * D_FF + n0 + (tx << 2)] = hv;
        }
    }
}

// out[token] = gate * ( h[row] @ W2[e] (D_FF x D_MODEL) + b2[e] )
__global__ __launch_bounds__(256) void ffn2_kernel(const float* __restrict__ W2,
                                                   const float* __restrict__ b2,
                                                   float* __restrict__ out) {
    const int e   = blockIdx.z;
    const int cnt = g_count[e];
    const int m0  = blockIdx.y * BM;
    if (m0 >= cnt) return;
    const int off = g_offset[e];
    const int n0  = blockIdx.x * BN;
    const float* W = W2 + (size_t)e * D_FF * D_MODEL;

    __shared__ float As[BK][BM + 4];
    __shared__ float Bs[BK][BN];

    const int t  = threadIdx.x;
    const int tx = t & 15;
    const int ty = t >> 4;

    const int am = t >> 2;
    const int ak = (t & 3) << 2;
    const int gm_a  = m0 + am;
    const bool a_ok = gm_a < cnt;
    const float* hrow = g_h + (size_t)(off + (a_ok ? gm_a : 0)) * D_FF;

    const int bk = t >> 4;
    const int bn = (t & 15) << 2;

    float acc[4][4] = {};

    for (int k0 = 0; k0 < D_FF; k0 += BK) {
        float4 av = a_ok ? *(const float4*)(hrow + k0 + ak)
                         : make_float4(0.f, 0.f, 0.f, 0.f);
        As[ak + 0][am] = av.x;
        As[ak + 1][am] = av.y;
        As[ak + 2][am] = av.z;
        As[ak + 3][am] = av.w;
        float4 bv = *(const float4*)(W + (size_t)(k0 + bk) * D_MODEL + n0 + bn);
        *(float4*)&Bs[bk][bn] = bv;
        __syncthreads();
#pragma unroll
        for (int k = 0; k < BK; k++) {
            float4 a = *(const float4*)&As[k][ty << 2];
            float4 b = *(const float4*)&Bs[k][tx << 2];
            float aa[4] = {a.x, a.y, a.z, a.w};
            float bb[4] = {b.x, b.y, b.z, b.w};
#pragma unroll
            for (int i = 0; i < 4; i++)
#pragma unroll
                for (int j = 0; j < 4; j++) acc[i][j] += aa[i] * bb[j];
        }
        __syncthreads();
    }

    const float4 bias = *(const float4*)(b2 + (size_t)e * D_MODEL + n0 + (tx << 2));
    const float bb[4] = {bias.x, bias.y, bias.z, bias.w};
#pragma unroll
    for (int i = 0; i < 4; i++) {
        int gm = m0 + (ty << 2) + i;
        if (gm < cnt) {
            int token = g_perm[off + gm];
            float gate = g_gate[token];
            float4 ov;
            ov.x = gate * (acc[i][0] + bb[0]);
            ov.y = gate * (acc[i][1] + bb[1]);
            ov.z = gate * (acc[i][2] + bb[2]);
            ov.w = gate * (acc[i][3] + bb[3]);
            *(float4*)&out[(size_t)token * D_MODEL + n0 + (tx << 2)] = ov;
        }
    }
}

// ---------------- launcher ----------------
extern "C" void kernel_launch(void* const* d_in, const int* in_sizes, int n_in,
                              void* d_out, int out_size) {
    const float* x   = (const float*)d_in[0];   // [4,1024,1024]
    const float* rW  = (const float*)d_in[1];   // [1024,8]
    const float* rb  = (const float*)d_in[2];   // [8]
    const float* W1  = (const float*)d_in[3];   // [8,1024,4096]
    const float* b1  = (const float*)d_in[4];   // [8,4096]
    const float* W2  = (const float*)d_in[5];   // [8,4096,1024]
    const float* b2  = (const float*)d_in[6];   // [8,1024]
    float* out       = (float*)d_out;           // [4,1024,1024]

    zero_counts_kernel<<<1, 32>>>();
    router_kernel<<<(N_TOK * 32) / 256, 256>>>(x, rW, rb);
    offsets_kernel<<<1, 1>>>();
    perm_kernel<<<N_TOK / 256, 256>>>();

    dim3 g1(D_FF / BN, N_TOK / BM, N_EXP);      // (64, 64, 8); empty tiles early-exit
    ffn1_kernel<<<g1, 256>>>(x, W1, b1);

    dim3 g2(D_MODEL / BN, N_TOK / BM, N_EXP);   // (16, 64, 8)
    ffn2_kernel<<<g2, 256>>>(W2, b2, out);
}

// round 2
// speedup vs baseline: 3.2067x; 3.2067x over previous
#include <cuda_runtime.h>
#include <cuda_bf16.h>
#include <cstdint>

#define D_MODEL 1024
#define D_FF    4096
#define N_EXP   8
#define N_TOK   4096   // 4 * 1024

// ---------------- scratch (__device__ globals; no allocation allowed) ----------------
__device__ float g_gate[N_TOK];
__device__ int   g_expert[N_TOK];
__device__ int   g_pos[N_TOK];
__device__ int   g_count[N_EXP];
__device__ int   g_offset[N_EXP + 1];
__device__ int   g_perm[N_TOK];                       // gathered row -> token id
__device__ float g_h[(size_t)N_TOK * D_FF];           // 64 MB hidden activations

// ---------------- helpers ----------------
__device__ __forceinline__ uint32_t f2tf32(float f) {
    uint32_t u;
    asm("cvt.rna.tf32.f32 %0, %1;" : "=r"(u) : "f"(f));
    return u;
}

__device__ __forceinline__ void mma_tf32(float c[4], const uint32_t a[4], const uint32_t b[2]) {
    asm volatile(
        "mma.sync.aligned.m16n8k8.row.col.f32.tf32.tf32.f32 "
        "{%0,%1,%2,%3}, {%4,%5,%6,%7}, {%8,%9}, {%0,%1,%2,%3};\n"
        : "+f"(c[0]), "+f"(c[1]), "+f"(c[2]), "+f"(c[3])
        : "r"(a[0]), "r"(a[1]), "r"(a[2]), "r"(a[3]), "r"(b[0]), "r"(b[1]));
}

// ---------------- kernel 0: zero the per-expert counters ----------------
__global__ void zero_counts_kernel() {
    if (threadIdx.x < N_EXP) g_count[threadIdx.x] = 0;
}

// ---------------- kernel 1: router (one warp per token) ----------------
__global__ void router_kernel(const float* __restrict__ x,
                              const float* __restrict__ rW,
                              const float* __restrict__ rb) {
    int warp = (blockIdx.x * blockDim.x + threadIdx.x) >> 5;
    int lane = threadIdx.x & 31;
    if (warp >= N_TOK) return;
    const float* xr = x + (size_t)warp * D_MODEL;

    float acc[N_EXP];
#pragma unroll
    for (int e = 0; e < N_EXP; e++) acc[e] = 0.f;

    for (int d = lane; d < D_MODEL; d += 32) {
        float xv = xr[d];
        const float* w = rW + d * N_EXP;
#pragma unroll
        for (int e = 0; e < N_EXP; e++) acc[e] += xv * w[e];
    }
#pragma unroll
    for (int e = 0; e < N_EXP; e++) {
#pragma unroll
        for (int off = 16; off; off >>= 1)
            acc[e] += __shfl_xor_sync(0xffffffffu, acc[e], off);
    }
    if (lane == 0) {
        float mx = -1e30f; int arg = 0;
#pragma unroll
        for (int e = 0; e < N_EXP; e++) {
            float l = acc[e] + rb[e];
            acc[e] = l;
            if (l > mx) { mx = l; arg = e; }   // first-max tie-break like jnp.argmax
        }
        float s = 0.f;
#pragma unroll
        for (int e = 0; e < N_EXP; e++) s += expf(acc[e] - mx);
        float gate = 1.0f / s;  // softmax prob of the argmax entry
        int pos = atomicAdd(&g_count[arg], 1);
        g_gate[warp]   = gate;
        g_expert[warp] = arg;
        g_pos[warp]    = pos;
    }
}

// ---------------- kernel 2: exclusive scan over 8 counts ----------------
__global__ void offsets_kernel() {
    int s = 0;
    g_offset[0] = 0;
#pragma unroll
    for (int e = 0; e < N_EXP; e++) { s += g_count[e]; g_offset[e + 1] = s; }
}

// ---------------- kernel 3: build permutation (gathered row -> token) ----------------
__global__ void perm_kernel() {
    int t = blockIdx.x * blockDim.x + threadIdx.x;
    if (t >= N_TOK) return;
    g_perm[g_offset[g_expert[t]] + g_pos[t]] = t;
}

// ---------------- tf32 tensor-core GEMMs ----------------
// Tile: BM=128, BN=128, BK=32; 256 threads = 8 warps (2 x 4); warp tile 64x32.
#define BM 128
#define BN 128
#define BK 32
#define PADA 4    // As stride 36 floats: frag-load banks = (m*4+k)%32, all distinct
#define PADB 8    // Bs stride 136 floats: frag-load banks = (k*8+n)%32, all distinct

// h = relu( x_gathered[cnt, 1024] @ W1[e] + b1[e] ),  stored to g_h in gathered order
__global__ __launch_bounds__(256) void ffn1_kernel(const float* __restrict__ x,
                                                   const float* __restrict__ W1,
                                                   const float* __restrict__ b1) {
    const int e   = blockIdx.z;
    const int cnt = g_count[e];
    const int m0  = blockIdx.y * BM;
    if (m0 >= cnt) return;
    const int off = g_offset[e];
    const int n0  = blockIdx.x * BN;
    const float* W = W1 + (size_t)e * D_MODEL * D_FF;

    __shared__ float As[BM][BK + PADA];
    __shared__ float Bs[BK][BN + PADB];

    const int t    = threadIdx.x;
    const int lane = t & 31;
    const int wid  = t >> 5;
    const int wm   = (wid & 1) * 64;   // warp row base
    const int wn   = (wid >> 1) * 32;  // warp col base

    // ---- global-load thread mapping ----
    const int a_r  = t >> 3;          // 0..31 (+32*i for i in 0..3)
    const int a_c4 = (t & 7) * 4;
    const int b_r  = t >> 5;          // 0..7  (+8*j)
    const int b_c4 = (t & 31) * 4;

    const float* aptr[4];
    bool aok[4];
#pragma unroll
    for (int i = 0; i < 4; i++) {
        int lr = m0 + a_r + 32 * i;
        aok[i] = lr < cnt;
        aptr[i] = aok[i] ? (x + (size_t)g_perm[off + lr] * D_MODEL + a_c4) : x;
    }
    const float* bbase = W + n0 + b_c4;

    float4 aS[4], bS[4];

    auto LDG = [&](int k0) {
#pragma unroll
        for (int i = 0; i < 4; i++)
            aS[i] = aok[i] ? *(const float4*)(aptr[i] + k0)
                           : make_float4(0.f, 0.f, 0.f, 0.f);
#pragma unroll
        for (int j = 0; j < 4; j++)
            bS[j] = *(const float4*)(bbase + (size_t)(k0 + b_r + 8 * j) * D_FF);
    };
    auto STS = [&]() {
#pragma unroll
        for (int i = 0; i < 4; i++) {
            float4 v;
            v.x = __uint_as_float(f2tf32(aS[i].x));
            v.y = __uint_as_float(f2tf32(aS[i].y));
            v.z = __uint_as_float(f2tf32(aS[i].z));
            v.w = __uint_as_float(f2tf32(aS[i].w));
            *(float4*)&As[a_r + 32 * i][a_c4] = v;
        }
#pragma unroll
        for (int j = 0; j < 4; j++) {
            float4 v;
            v.x = __uint_as_float(f2tf32(bS[j].x));
            v.y = __uint_as_float(f2tf32(bS[j].y));
            v.z = __uint_as_float(f2tf32(bS[j].z));
            v.w = __uint_as_float(f2tf32(bS[j].w));
            *(float4*)&Bs[b_r + 8 * j][b_c4] = v;
        }
    };

    float acc[4][4][4] = {};

    const int KT = D_MODEL / BK;   // 32
    LDG(0);
    STS();
    __syncthreads();

    for (int kt = 0; kt < KT; kt++) {
        if (kt + 1 < KT) LDG((kt + 1) * BK);
#pragma unroll
        for (int kk = 0; kk < BK; kk += 8) {
            uint32_t af[4][4], bf[4][2];
            const int kc = kk + (lane & 3);
#pragma unroll
            for (int mt = 0; mt < 4; mt++) {
                const int r = wm + mt * 16 + (lane >> 2);
                af[mt][0] = __float_as_uint(As[r][kc]);
                af[mt][1] = __float_as_uint(As[r + 8][kc]);
                af[mt][2] = __float_as_uint(As[r][kc + 4]);
                af[mt][3] = __float_as_uint(As[r + 8][kc + 4]);
            }
#pragma unroll
            for (int nt = 0; nt < 4; nt++) {
                const int cc = wn + nt * 8 + (lane >> 2);
                bf[nt][0] = __float_as_uint(Bs[kc][cc]);
                bf[nt][1] = __float_as_uint(Bs[kc + 4][cc]);
            }
#pragma unroll
            for (int mt = 0; mt < 4; mt++)
#pragma unroll
                for (int nt = 0; nt < 4; nt++)
                    mma_tf32(acc[mt][nt], af[mt], bf[nt]);
        }
        __syncthreads();
        if (kt + 1 < KT) { STS(); __syncthreads(); }
    }

    // ---- epilogue: bias + relu, store to g_h ----
    const float* b1e = b1 + (size_t)e * D_FF;
#pragma unroll
    for (int mt = 0; mt < 4; mt++) {
        const int lr0 = m0 + wm + mt * 16 + (lane >> 2);
#pragma unroll
        for (int nt = 0; nt < 4; nt++) {
            const int gc = n0 + wn + nt * 8 + 2 * (lane & 3);
            const float2 bv = *(const float2*)(b1e + gc);
            if (lr0 < cnt) {
                float2 o;
                o.x = fmaxf(acc[mt][nt][0] + bv.x, 0.f);
                o.y = fmaxf(acc[mt][nt][1] + bv.y, 0.f);
                *(float2*)&g_h[(size_t)(off + lr0) * D_FF + gc] = o;
            }
            if (lr0 + 8 < cnt) {
                float2 o;
                o.x = fmaxf(acc[mt][nt][2] + bv.x, 0.f);
                o.y = fmaxf(acc[mt][nt][3] + bv.y, 0.f);
                *(float2*)&g_h[(size_t)(off + lr0 + 8) * D_FF + gc] = o;
            }
        }
    }
}

// out[token] = gate * ( h_gathered[cnt, 4096] @ W2[e] + b2[e] )
__global__ __launch_bounds__(256) void ffn2_kernel(const float* __restrict__ W2,
                                                   const float* __restrict__ b2,
                                                   float* __restrict__ out) {
    const int e   = blockIdx.z;
    const int cnt = g_count[e];
    const int m0  = blockIdx.y * BM;
    if (m0 >= cnt) return;
    const int off = g_offset[e];
    const int n0  = blockIdx.x * BN;
    const float* W = W2 + (size_t)e * D_FF * D_MODEL;

    __shared__ float As[BM][BK + PADA];
    __shared__ float Bs[BK][BN + PADB];

    const int t    = threadIdx.x;
    const int lane = t & 31;
    const int wid  = t >> 5;
    const int wm   = (wid & 1) * 64;
    const int wn   = (wid >> 1) * 32;

    const int a_r  = t >> 3;
    const int a_c4 = (t & 7) * 4;
    const int b_r  = t >> 5;
    const int b_c4 = (t & 31) * 4;

    const float* aptr[4];
    bool aok[4];
#pragma unroll
    for (int i = 0; i < 4; i++) {
        int lr = m0 + a_r + 32 * i;
        aok[i] = lr < cnt;
        aptr[i] = aok[i] ? (g_h + (size_t)(off + lr) * D_FF + a_c4) : g_h;
    }
    const float* bbase = W + n0 + b_c4;

    float4 aS[4], bS[4];

    auto LDG = [&](int k0) {
#pragma unroll
        for (int i = 0; i < 4; i++)
            aS[i] = aok[i] ? *(const float4*)(aptr[i] + k0)
                           : make_float4(0.f, 0.f, 0.f, 0.f);
#pragma unroll
        for (int j = 0; j < 4; j++)
            bS[j] = *(const float4*)(bbase + (size_t)(k0 + b_r + 8 * j) * D_MODEL);
    };
    auto STS = [&]() {
#pragma unroll
        for (int i = 0; i < 4; i++) {
            float4 v;
            v.x = __uint_as_float(f2tf32(aS[i].x));
            v.y = __uint_as_float(f2tf32(aS[i].y));
            v.z = __uint_as_float(f2tf32(aS[i].z));
            v.w = __uint_as_float(f2tf32(aS[i].w));
            *(float4*)&As[a_r + 32 * i][a_c4] = v;
        }
#pragma unroll
        for (int j = 0; j < 4; j++) {
            float4 v;
            v.x = __uint_as_float(f2tf32(bS[j].x));
            v.y = __uint_as_float(f2tf32(bS[j].y));
            v.z = __uint_as_float(f2tf32(bS[j].z));
            v.w = __uint_as_float(f2tf32(bS[j].w));
            *(float4*)&Bs[b_r + 8 * j][b_c4] = v;
        }
    };

    float acc[4][4][4] = {};

    const int KT = D_FF / BK;   // 128
    LDG(0);
    STS();
    __syncthreads();

    for (int kt = 0; kt < KT; kt++) {
        if (kt + 1 < KT) LDG((kt + 1) * BK);
#pragma unroll
        for (int kk = 0; kk < BK; kk += 8) {
            uint32_t af[4][4], bf[4][2];
            const int kc = kk + (lane & 3);
#pragma unroll
            for (int mt = 0; mt < 4; mt++) {
                const int r = wm + mt * 16 + (lane >> 2);
                af[mt][0] = __float_as_uint(As[r][kc]);
                af[mt][1] = __float_as_uint(As[r + 8][kc]);
                af[mt][2] = __float_as_uint(As[r][kc + 4]);
                af[mt][3] = __float_as_uint(As[r + 8][kc + 4]);
            }
#pragma unroll
            for (int nt = 0; nt < 4; nt++) {
                const int cc = wn + nt * 8 + (lane >> 2);
                bf[nt][0] = __float_as_uint(Bs[kc][cc]);
                bf[nt][1] = __float_as_uint(Bs[kc + 4][cc]);
            }
#pragma unroll
            for (int mt = 0; mt < 4; mt++)
#pragma unroll
                for (int nt = 0; nt < 4; nt++)
                    mma_tf32(acc[mt][nt], af[mt], bf[nt]);
        }
        __syncthreads();
        if (kt + 1 < KT) { STS(); __syncthreads(); }
    }

    // ---- epilogue: bias + gate, scatter to out ----
    const float* b2e = b2 + (size_t)e * D_MODEL;
#pragma unroll
    for (int mt = 0; mt < 4; mt++) {
        const int lr0 = m0 + wm + mt * 16 + (lane >> 2);
#pragma unroll
        for (int nt = 0; nt < 4; nt++) {
            const int gc = n0 + wn + nt * 8 + 2 * (lane & 3);
            const float2 bv = *(const float2*)(b2e + gc);
            if (lr0 < cnt) {
                int tok = g_perm[off + lr0];
                float gg = g_gate[tok];
                float2 o;
                o.x = gg * (acc[mt][nt][0] + bv.x);
                o.y = gg * (acc[mt][nt][1] + bv.y);
                *(float2*)&out[(size_t)tok * D_MODEL + gc] = o;
            }
            if (lr0 + 8 < cnt) {
                int tok = g_perm[off + lr0 + 8];
                float gg = g_gate[tok];
                float2 o;
                o.x = gg * (acc[mt][nt][2] + bv.x);
                o.y = gg * (acc[mt][nt][3] + bv.y);
                *(float2*)&out[(size_t)tok * D_MODEL + gc] = o;
            }
        }
    }
}

// ---------------- launcher ----------------
extern "C" void kernel_launch(void* const* d_in, const int* in_sizes, int n_in,
                              void* d_out, int out_size) {
    const float* x   = (const float*)d_in[0];   // [4,1024,1024]
    const float* rW  = (const float*)d_in[1];   // [1024,8]
    const float* rb  = (const float*)d_in[2];   // [8]
    const float* W1  = (const float*)d_in[3];   // [8,1024,4096]
    const float* b1  = (const float*)d_in[4];   // [8,4096]
    const float* W2  = (const float*)d_in[5];   // [8,4096,1024]
    const float* b2  = (const float*)d_in[6];   // [8,1024]
    float* out       = (float*)d_out;           // [4,1024,1024]

    zero_counts_kernel<<<1, 32>>>();
    router_kernel<<<(N_TOK * 32) / 256, 256>>>(x, rW, rb);
    offsets_kernel<<<1, 1>>>();
    perm_kernel<<<N_TOK / 256, 256>>>();

    dim3 g1(D_FF / BN, N_TOK / BM, N_EXP);      // (32, 32, 8); empty tiles early-exit
    ffn1_kernel<<<g1, 256>>>(x, W1, b1);

    dim3 g2(D_MODEL / BN, N_TOK / BM, N_EXP);   // (8, 32, 8)
    ffn2_kernel<<<g2, 256>>>(W2, b2, out);
}